// round 17
// baseline (speedup 1.0000x reference)
#include <cuda_runtime.h>
#include <math.h>

// B=16, K=16 steps, N=1024, D=256, L=8.  16 clusters (1/batch) x 8 CTAs (1/n-chunk of 128).
#define S_ELEMS (16*16*8*256)

// ---------------- scratch ----------------
__device__ __align__(16) float g_slots[128*256];
__device__ __align__(16) float g_Mcomb[256*1024];   // [k][0:256]=Wq^T Wk*scale, [k][256:1024]=W_hh^T
__device__ __align__(16) float g_cpart[8*1024];     // 8 e-partials of [scale*bq@Wk | b_hh]
__device__ __align__(16) float g_M2T[256*768];      // (W_ih @ Wv)^T  [k][c]
__device__ __align__(16) float g_c2part[8*768];     // 8 e-partials of (W_ih@bv + b_ih)
__device__ __align__(16) float g_qtgh[128*1024];    // [row][0:256]=Qt, [256:1024]=gh
__device__ __align__(16) float g_pmax[128*8];
__device__ __align__(16) float g_psum[128*8];
__device__ __align__(16) float g_upart[128*8*256];  // [(b*8+chunk)*8+s][j] unnormalized expP@H
__device__ __align__(16) float g_gi[128*768];
__device__ __align__(16) float g_h1[128*256];       // relu'd ffn1
__device__ __align__(16) float g_ffn2[128*256];

__device__ __forceinline__ float sigm(float x) { return 1.f / (1.f + expf(-x)); }

// ============ 32x32-tile GEMM (precompute only), AT/BT variants ============
template<int AT, int BT>
__device__ __forceinline__ void gemm_pre(
    int m0, int c0,
    const float* __restrict__ A, int lda,
    const float* __restrict__ B, int ldb,
    float* __restrict__ C, int ldc, float alpha)
{
    __shared__ float As[32][33];
    __shared__ __align__(16) float Bs[32][36];
    const int tid = threadIdx.x;
    const int row = tid & 31, cg = tid >> 5;
    float a0 = 0.f, a1 = 0.f, a2 = 0.f, a3 = 0.f;
    for (int k0 = 0; k0 < 256; k0 += 32) {
        if (AT) {
            int r = tid & 31, e = tid >> 5;
            #pragma unroll
            for (int i = 0; i < 4; i++) { int ee = e + i*8; As[r][ee] = A[(size_t)(k0+ee)*lda + m0 + r]; }
        } else {
            int e = tid & 31, r = tid >> 5;
            #pragma unroll
            for (int i = 0; i < 4; i++) { int rr = r + i*8; As[rr][e] = A[(size_t)(m0+rr)*lda + k0 + e]; }
        }
        if (BT) {
            int e = tid & 31, cc = tid >> 5;
            #pragma unroll
            for (int i = 0; i < 4; i++) { int c = cc + i*8; Bs[e][c] = B[(size_t)(c0+c)*ldb + k0 + e]; }
        } else {
            int c = tid & 31, e = tid >> 5;
            #pragma unroll
            for (int i = 0; i < 4; i++) { int ee = e + i*8; Bs[ee][c] = B[(size_t)(k0+ee)*ldb + c0 + c]; }
        }
        __syncthreads();
        #pragma unroll
        for (int e = 0; e < 32; e++) {
            float a = As[row][e];
            float4 b4 = *(const float4*)&Bs[e][cg*4];
            a0 = fmaf(a,b4.x,a0); a1 = fmaf(a,b4.y,a1); a2 = fmaf(a,b4.z,a2); a3 = fmaf(a,b4.w,a3);
        }
        __syncthreads();
    }
    int cb = c0 + cg*4;
    *(float4*)&C[(size_t)(m0+row)*ldc + cb] = make_float4(a0*alpha, a1*alpha, a2*alpha, a3*alpha);
}

// ================= precompute (2 kernels) =================
__global__ void pre_misc(const float* __restrict__ eps, const float* __restrict__ mu,
                         const float* __restrict__ ls, const float* __restrict__ W_hh,
                         const float* __restrict__ bq, const float* __restrict__ Wk,
                         const float* __restrict__ b_hh, const float* __restrict__ W_ih,
                         const float* __restrict__ bv, const float* __restrict__ b_ih)
{
    const int bx = blockIdx.x, tid = threadIdx.x;
    if (bx < 128) {
        int i = bx * 256 + tid;
        int ld = i & 2047;
        g_slots[i] = mu[ld] + expf(ls[ld]) * eps[i];
    } else if (bx < 320) {
        __shared__ float Ts[32][33];
        int bx2 = bx - 128;
        int tc = (bx2 % 24) * 32, tk = (bx2 / 24) * 32;
        int r = tid >> 5, col = tid & 31;
        #pragma unroll
        for (int i = 0; i < 4; i++) {
            int rr = r + i*8;
            Ts[rr][col] = W_hh[(size_t)(tc + rr) * 256 + tk + col];
        }
        __syncthreads();
        #pragma unroll
        for (int i = 0; i < 4; i++) {
            int kr = r + i*8;
            g_Mcomb[(size_t)(tk + kr) * 1024 + 256 + tc + col] = Ts[col][kr];
        }
    } else if (bx < 352) {
        int q = bx - 320;
        int p = q >> 2;
        int c = (q & 3) * 256 + tid;
        if (c < 256) {
            int e0 = p * 32;
            float s = 0.f;
            #pragma unroll 8
            for (int e = 0; e < 32; e++) s = fmaf(bq[e0+e], Wk[(e0+e)*256 + c], s);
            g_cpart[p * 1024 + c] = s * 0.0625f;
        } else {
            g_cpart[p * 1024 + c] = (p == 0) ? b_hh[c - 256] : 0.f;
        }
    } else {
        int q = bx - 352;
        int p = q / 3;
        int c = (q % 3) * 256 + tid;
        int e0 = p * 32;
        float s = (p == 0) ? b_ih[c] : 0.f;
        #pragma unroll 8
        for (int e = 0; e < 32; e++) s = fmaf(W_ih[c*256 + e0+e], bv[e0+e], s);
        g_c2part[p * 768 + c] = s;
    }
}

// grid(24,16): y<8 & x<8 -> Mcomb Q-part; y>=8 -> M2T = Wv^T @ W_ih^T  [256][768]
__global__ void pre_gemm(const float* __restrict__ Wq, const float* __restrict__ Wk,
                         const float* __restrict__ W_ih, const float* __restrict__ Wv)
{
    if (blockIdx.y < 8) {
        if (blockIdx.x >= 8) return;
        gemm_pre<1,0>(blockIdx.y*32, blockIdx.x*32, Wq,256, Wk,256, g_Mcomb,1024, 0.0625f);
    } else {
        gemm_pre<1,1>((blockIdx.y-8)*32, blockIdx.x*32, Wv,256, W_ih,256, g_M2T,768, 1.f);
    }
}

// ================= cluster megakernel =================
__global__ void __cluster_dims__(8,1,1) __launch_bounds__(512)
mega_kernel(const float* __restrict__ H,
            const float* __restrict__ W1, const float* __restrict__ b1,
            const float* __restrict__ W2, const float* __restrict__ b2,
            const float* __restrict__ lg, const float* __restrict__ lb,
            float* __restrict__ outS, float* __restrict__ outB)
{
    __shared__ __align__(16) float slotsT[2048];   // [d][r] k-major slots of this batch
    __shared__ __align__(16) float s2T[2048];      // [d][r] (UcombT in P3, Qs in P2)
    __shared__ __align__(16) float attnT[1024];    // [n][s] (h1red in P4/P5)
    __shared__ __align__(16) float scr[4608];      // Hs(pitch36) / Bs / Bs2+h1T
    __shared__ float extra[128];

    const int bid = blockIdx.x, tid = threadIdx.x;
    const int b = bid >> 3, c = bid & 7;

    auto csync = [&]() {
        asm volatile("barrier.cluster.arrive.aligned;" ::: "memory");
        asm volatile("barrier.cluster.wait.aligned;" ::: "memory");
    };

    // load slots (batch b) into smem k-major
    #pragma unroll
    for (int it = 0; it < 4; it++) {
        int q = tid + it*512;                    // q = d*8 + r
        slotsT[q] = __ldcg(&g_slots[(size_t)(b*8 + (q & 7))*256 + (q >> 3)]);
    }
    __syncthreads();

    #pragma unroll 1
    for (int t = 0; t < 16; t++) {
        // ---------- P1: qtgh[8][c*128..] = slots @ Mcomb + ccomb, K=256 ----------
        {
            float* Bs = scr;                     // [32][128]
            const int row = tid & 7, cg = tid >> 3;   // cg 0..63
            const int col0 = c*128 + cg*2;
            float acc0 = 0.f, acc1 = 0.f;
            for (int k0 = 0; k0 < 256; k0 += 32) {
                __syncthreads();
                #pragma unroll
                for (int it = 0; it < 2; it++) {
                    int q = tid + it*512;        // 1024 float4
                    int e = q >> 5, j4 = q & 31;
                    *(float4*)&Bs[e*128 + j4*4] =
                        *(const float4*)&g_Mcomb[(size_t)(k0+e)*1024 + c*128 + j4*4];
                }
                __syncthreads();
                #pragma unroll
                for (int e = 0; e < 32; e++) {
                    float a = slotsT[(k0+e)*8 + row];
                    float2 b2v = *(const float2*)&Bs[e*128 + cg*2];
                    acc0 = fmaf(a, b2v.x, acc0);
                    acc1 = fmaf(a, b2v.y, acc1);
                }
            }
            #pragma unroll
            for (int p = 0; p < 8; p++) {
                acc0 += g_cpart[p*1024 + col0];
                acc1 += g_cpart[p*1024 + col0 + 1];
            }
            *(float2*)&g_qtgh[(size_t)(b*8+row)*1024 + col0] = make_float2(acc0, acc1);
        }
        csync();  // #1

        // ---------- P2: scores + chunk stats + exp.H partials (chunk c) ----------
        {
            float* Qs   = s2T;                   // 2048
            float* Hs   = scr;                   // [128][36] per 32-d tile (float4-aligned pitch)
            float* redM = extra;                 // 32
            float* redS = extra + 32;            // 32
            float* mrow = extra + 64;            // 8
            const int nl = tid & 127, sg = tid >> 7, lane = tid & 31, w = tid >> 5;

            {   int s = tid >> 6, d4 = tid & 63;
                float4 x = __ldcg((const float4*)&g_qtgh[(size_t)(b*8+s)*1024 + d4*4]);
                *(float4*)&Qs[s*256 + d4*4] = x;
            }
            const float* hb = H + ((size_t)(b*16 + t)*1024 + c*128) * 256;
            float a0 = 0.f, a1 = 0.f;
            for (int d0 = 0; d0 < 256; d0 += 32) {
                __syncthreads();
                #pragma unroll
                for (int it = 0; it < 2; it++) {
                    int q = tid + it*512;        // 1024 float4: n = q>>3, d4b = q&7
                    int n = q >> 3, d4b = q & 7;
                    *(float4*)&Hs[n*36 + d4b*4] =
                        *(const float4*)&hb[(size_t)n*256 + d0 + d4b*4];
                }
                __syncthreads();
                #pragma unroll
                for (int dd = 0; dd < 32; dd += 4) {
                    float4 h4 = *(const float4*)&Hs[nl*36 + dd];
                    float4 q0 = *(const float4*)&Qs[(sg*2+0)*256 + d0 + dd];
                    float4 q1 = *(const float4*)&Qs[(sg*2+1)*256 + d0 + dd];
                    a0 = fmaf(h4.x,q0.x,a0); a0 = fmaf(h4.y,q0.y,a0);
                    a0 = fmaf(h4.z,q0.z,a0); a0 = fmaf(h4.w,q0.w,a0);
                    a1 = fmaf(h4.x,q1.x,a1); a1 = fmaf(h4.y,q1.y,a1);
                    a1 = fmaf(h4.z,q1.z,a1); a1 = fmaf(h4.w,q1.w,a1);
                }
            }
            #pragma unroll
            for (int i = 0; i < 2; i++) {
                float m = i ? a1 : a0;
                #pragma unroll
                for (int o = 16; o > 0; o >>= 1) m = fmaxf(m, __shfl_xor_sync(0xffffffffu, m, o));
                if (lane == 0) redM[(sg*2+i)*4 + (w & 3)] = m;
            }
            __syncthreads();
            if (tid < 8) {
                float m = fmaxf(fmaxf(redM[tid*4], redM[tid*4+1]), fmaxf(redM[tid*4+2], redM[tid*4+3]));
                mrow[tid] = m;
                g_pmax[(b*8 + tid)*8 + c] = m;
            }
            __syncthreads();
            float e0v = expf(a0 - mrow[sg*2+0]);
            float e1v = expf(a1 - mrow[sg*2+1]);
            attnT[nl*8 + sg*2+0] = e0v;
            attnT[nl*8 + sg*2+1] = e1v;
            #pragma unroll
            for (int i = 0; i < 2; i++) {
                float e = i ? e1v : e0v;
                #pragma unroll
                for (int o = 16; o > 0; o >>= 1) e += __shfl_xor_sync(0xffffffffu, e, o);
                if (lane == 0) redS[(sg*2+i)*4 + (w & 3)] = e;
            }
            __syncthreads();
            if (tid < 8)
                g_psum[(b*8 + tid)*8 + c] = redS[tid*4] + redS[tid*4+1] + redS[tid*4+2] + redS[tid*4+3];

            // column pass (coalesced over j, H L1-hot)
            const int j = tid & 255, sh = tid >> 8;
            float acc[4] = {0.f,0.f,0.f,0.f};
            #pragma unroll 8
            for (int n = 0; n < 128; n++) {
                float hv = __ldg(&hb[(size_t)n*256 + j]);
                float4 e4 = *(const float4*)&attnT[n*8 + sh*4];
                acc[0] = fmaf(e4.x, hv, acc[0]);
                acc[1] = fmaf(e4.y, hv, acc[1]);
                acc[2] = fmaf(e4.z, hv, acc[2]);
                acc[3] = fmaf(e4.w, hv, acc[3]);
            }
            #pragma unroll
            for (int s4 = 0; s4 < 4; s4++)
                g_upart[((size_t)(b*8 + c)*8 + sh*4 + s4)*256 + j] = acc[s4];
        }
        csync();  // #2

        // ---------- P3: flash-combine U + gi[8][c*96..] = U @ M2T + c2, K=256 ----------
        {
            float* UcombT = s2T;                 // [k][r]
            float* Bs = scr;                     // [32][96]
            float* ws = extra;                   // [8][8]
            if (tid < 8) {
                int r = b*8 + tid;
                float pm[8];
                #pragma unroll
                for (int p = 0; p < 8; p++) pm[p] = __ldcg(&g_pmax[r*8 + p]);
                float m = pm[0];
                #pragma unroll
                for (int p = 1; p < 8; p++) m = fmaxf(m, pm[p]);
                float S = 0.f;
                #pragma unroll
                for (int p = 0; p < 8; p++) S += __ldcg(&g_psum[r*8 + p]) * expf(pm[p] - m);
                float invS = 1.f / S;
                #pragma unroll
                for (int p = 0; p < 8; p++) ws[tid*8 + p] = expf(pm[p] - m) * invS;
            }
            __syncthreads();
            #pragma unroll
            for (int it = 0; it < 4; it++) {
                int q = tid + it*512;            // r = q>>8, k = q&255
                int r = q >> 8, k = q & 255;
                float v = 0.f;
                #pragma unroll
                for (int p = 0; p < 8; p++)
                    v = fmaf(__ldcg(&g_upart[((size_t)(b*8 + p)*8 + r)*256 + k]), ws[r*8 + p], v);
                UcombT[k*8 + r] = v;
            }
            const int row = tid & 7, cg = tid >> 3;   // cg 0..63, active cg<48
            const bool act = cg < 48;
            const int col0 = c*96 + cg*2;
            float acc0 = 0.f, acc1 = 0.f;
            for (int k0 = 0; k0 < 256; k0 += 32) {
                __syncthreads();
                for (int q = tid; q < 768; q += 512) {   // 768 float4 = 32e x 24j4
                    int e = q / 24, j4 = q % 24;
                    *(float4*)&Bs[e*96 + j4*4] =
                        *(const float4*)&g_M2T[(size_t)(k0+e)*768 + c*96 + j4*4];
                }
                __syncthreads();
                if (act) {
                    #pragma unroll
                    for (int e = 0; e < 32; e++) {
                        float a = UcombT[(k0+e)*8 + row];
                        float2 b2v = *(const float2*)&Bs[e*96 + cg*2];
                        acc0 = fmaf(a, b2v.x, acc0);
                        acc1 = fmaf(a, b2v.y, acc1);
                    }
                }
            }
            if (act) {
                #pragma unroll
                for (int p = 0; p < 8; p++) {
                    acc0 += g_c2part[p*768 + col0];
                    acc1 += g_c2part[p*768 + col0 + 1];
                }
                *(float2*)&g_gi[(size_t)(b*8+row)*768 + col0] = make_float2(acc0, acc1);
            }
        }
        csync();  // #3

        // ---------- P4: GRU s2 + Beta chunk + ffn1 slice (cols c*32..), K=256 ----------
        {
            float* Bs2   = scr;                  // [64][33] = 2112
            float* wsB   = extra;                // 8
            float* h1red = attnT;                // reuse AFTER beta write
            if (tid < 8) {
                int r = b*8 + tid;
                float pm[8];
                #pragma unroll
                for (int p = 0; p < 8; p++) pm[p] = __ldcg(&g_pmax[r*8 + p]);
                float m = pm[0];
                #pragma unroll
                for (int p = 1; p < 8; p++) m = fmaxf(m, pm[p]);
                float S = 0.f;
                #pragma unroll
                for (int p = 0; p < 8; p++) S += __ldcg(&g_psum[r*8 + p]) * expf(pm[p] - m);
                wsB[tid] = expf(pm[c] - m) / S;
            }
            // s2 (once per element) into s2T
            #pragma unroll
            for (int it = 0; it < 4; it++) {
                int q = tid + it*512;
                int r = q >> 8, d = q & 255;
                int gr = b*8 + r;
                float gir = __ldcg(&g_gi[(size_t)gr*768 + d]);
                float giz = __ldcg(&g_gi[(size_t)gr*768 + 256 + d]);
                float gin = __ldcg(&g_gi[(size_t)gr*768 + 512 + d]);
                float ghr = __ldcg(&g_qtgh[(size_t)gr*1024 + 256 + d]);
                float ghz = __ldcg(&g_qtgh[(size_t)gr*1024 + 512 + d]);
                float ghn = __ldcg(&g_qtgh[(size_t)gr*1024 + 768 + d]);
                float rg = sigm(gir + ghr);
                float z  = sigm(giz + ghz);
                float nn = tanhf(gin + rg * ghn);
                s2T[d*8 + r] = (1.f - z) * nn + z * slotsT[d*8 + r];
            }
            __syncthreads();
            // Beta chunk c (uses attnT before it is recycled)
            #pragma unroll
            for (int it = 0; it < 2; it++) {
                int q = tid + it*512;            // s = q>>7, n = q&127
                int s = q >> 7, n = q & 127;
                outB[(size_t)((b*16 + t)*8 + s)*1024 + c*128 + n] = attnT[n*8 + s] * wsB[s];
            }
            // ffn1 slice: rows 8 x cols 32, k-split 2
            const int row = (tid >> 5) & 7, col = tid & 31, ks = tid >> 8;
            float acc = 0.f;
            for (int t4 = 0; t4 < 4; t4++) {
                __syncthreads();
                {   int q = tid;                 // 512 float4: col=q>>4, k4=q&15
                    int cc = q >> 4, k4 = q & 15;
                    float4 v = *(const float4*)&W1[(size_t)(c*32+cc)*256 + t4*64 + k4*4];
                    Bs2[(k4*4+0)*33 + cc] = v.x;
                    Bs2[(k4*4+1)*33 + cc] = v.y;
                    Bs2[(k4*4+2)*33 + cc] = v.z;
                    Bs2[(k4*4+3)*33 + cc] = v.w;
                }
                __syncthreads();
                if ((t4 >> 1) == ks) {
                    #pragma unroll
                    for (int e = 0; e < 64; e++)
                        acc = fmaf(s2T[(t4*64 + e)*8 + row], Bs2[e*33 + col], acc);
                }
            }
            __syncthreads();
            h1red[ks*256 + (tid & 255)] = acc;
            __syncthreads();
            if (tid < 256) {
                float v = h1red[tid] + h1red[256 + tid] + b1[c*32 + (tid & 31)];
                g_h1[(size_t)(b*8 + (tid >> 5))*256 + c*32 + (tid & 31)] = fmaxf(v, 0.f);
            }
        }
        csync();  // #4

        // ---------- P5: ffn2 slice (cols c*32..), K=256 ----------
        {
            float* Bs2 = scr;                    // [64][33]
            float* h1T = scr + 2112;             // [k][r] 2048
            float* h2red = attnT;
            #pragma unroll
            for (int it = 0; it < 4; it++) {
                int q = tid + it*512;            // q = k*8 + r
                h1T[q] = __ldcg(&g_h1[(size_t)(b*8 + (q & 7))*256 + (q >> 3)]);
            }
            const int row = (tid >> 5) & 7, col = tid & 31, ks = tid >> 8;
            float acc = 0.f;
            for (int t4 = 0; t4 < 4; t4++) {
                __syncthreads();
                {   int q = tid;
                    int cc = q >> 4, k4 = q & 15;
                    float4 v = *(const float4*)&W2[(size_t)(c*32+cc)*256 + t4*64 + k4*4];
                    Bs2[(k4*4+0)*33 + cc] = v.x;
                    Bs2[(k4*4+1)*33 + cc] = v.y;
                    Bs2[(k4*4+2)*33 + cc] = v.z;
                    Bs2[(k4*4+3)*33 + cc] = v.w;
                }
                __syncthreads();
                if ((t4 >> 1) == ks) {
                    #pragma unroll
                    for (int e = 0; e < 64; e++)
                        acc = fmaf(h1T[(t4*64 + e)*8 + row], Bs2[e*33 + col], acc);
                }
            }
            __syncthreads();
            h2red[ks*256 + (tid & 255)] = acc;
            __syncthreads();
            if (tid < 256)
                g_ffn2[(size_t)(b*8 + (tid >> 5))*256 + c*32 + (tid & 31)] =
                    h2red[tid] + h2red[256 + tid];
        }
        csync();  // #5

        // ---------- P6: residual + LN; update slotsT (all CTAs); write outS slice ----------
        {
            float* rs = extra;                   // [8][2]
            float* rq = extra + 16;              // [8][2]
            const int row = tid >> 6, i6 = tid & 63;
            const int col0 = i6 * 4;
            float4 f2 = __ldcg((const float4*)&g_ffn2[(size_t)(b*8+row)*256 + col0]);
            float4 b4 = *(const float4*)&b2[col0];
            float x0 = s2T[(col0+0)*8 + row] + f2.x + b4.x;
            float x1 = s2T[(col0+1)*8 + row] + f2.y + b4.y;
            float x2 = s2T[(col0+2)*8 + row] + f2.z + b4.z;
            float x3 = s2T[(col0+3)*8 + row] + f2.w + b4.w;
            float s = x0+x1+x2+x3;
            float q = x0*x0 + x1*x1 + x2*x2 + x3*x3;
            #pragma unroll
            for (int o = 16; o > 0; o >>= 1) {
                s += __shfl_xor_sync(0xffffffffu, s, o);
                q += __shfl_xor_sync(0xffffffffu, q, o);
            }
            __syncthreads();
            if ((tid & 31) == 0) { rs[row*2 + (i6 >> 5)] = s; rq[row*2 + (i6 >> 5)] = q; }
            __syncthreads();
            float ts = rs[row*2] + rs[row*2+1];
            float tq = rq[row*2] + rq[row*2+1];
            float mean = ts * (1.f/256.f);
            float var  = tq * (1.f/256.f) - mean*mean;
            float inv  = rsqrtf(var + 1e-5f);
            float4 g4 = *(const float4*)&lg[col0];
            float4 l4 = *(const float4*)&lb[col0];
            float y0 = (x0 - mean)*inv*g4.x + l4.x;
            float y1 = (x1 - mean)*inv*g4.y + l4.y;
            float y2 = (x2 - mean)*inv*g4.z + l4.z;
            float y3 = (x3 - mean)*inv*g4.w + l4.w;
            __syncthreads();
            slotsT[(col0+0)*8 + row] = y0;
            slotsT[(col0+1)*8 + row] = y1;
            slotsT[(col0+2)*8 + row] = y2;
            slotsT[(col0+3)*8 + row] = y3;
            if ((i6 >> 3) == c)
                *(float4*)&outS[(size_t)((b*16 + t)*8 + row)*256 + col0] =
                    make_float4(y0, y1, y2, y3);
        }
        __syncthreads();   // slotsT complete before next-step P1
    }
}

// ================= launcher =================
extern "C" void kernel_launch(void* const* d_in, const int* in_sizes, int n_in,
                              void* d_out, int out_size)
{
    const float* H    = (const float*)d_in[0];
    const float* eps  = (const float*)d_in[1];
    const float* mu   = (const float*)d_in[2];
    const float* ls   = (const float*)d_in[3];
    const float* Wq   = (const float*)d_in[4];
    const float* bq   = (const float*)d_in[5];
    const float* Wk   = (const float*)d_in[6];
    // d_in[7] = bk: row-constant in logits, cancels in softmax — provably unused.
    const float* Wv   = (const float*)d_in[8];
    const float* bv   = (const float*)d_in[9];
    const float* W_ih = (const float*)d_in[10];
    const float* b_ih = (const float*)d_in[11];
    const float* W_hh = (const float*)d_in[12];
    const float* b_hh = (const float*)d_in[13];
    const float* W1   = (const float*)d_in[14];
    const float* b1   = (const float*)d_in[15];
    const float* W2   = (const float*)d_in[16];
    const float* b2   = (const float*)d_in[17];
    const float* lng  = (const float*)d_in[18];
    const float* lnb  = (const float*)d_in[19];

    float* outS = (float*)d_out;
    float* outB = outS + S_ELEMS;

    pre_misc<<<376, 256>>>(eps, mu, ls, W_hh, bq, Wk, b_hh, W_ih, bv, b_ih);
    pre_gemm<<<dim3(24, 16), 256>>>(Wq, Wk, W_ih, Wv);
    mega_kernel<<<128, 512>>>(H, W1, b1, W2, b2, lng, lnb, outS, outB);
}